// round 2
// baseline (speedup 1.0000x reference)
#include <cuda_runtime.h>
#include <cuda_bf16.h>
#include <cstdint>

// out = x @ Q per group, where Q = H_0 H_1 ... H_127 (Householder composition).
// Kernel A builds Q per group (rows evolve independently -> parallel scan, no barriers).
// Kernel B is a dense fp32 GEMM using packed fma.rn.f32x2 (Blackwell packed FP32).

#define G 16
#define MROWS 16384
#define C 128

typedef unsigned long long ull;

__device__ float Qbuf[G * C * C];  // 1 MB scratch for the composed reflectors

// ---------------- packed f32x2 helpers ----------------
__device__ __forceinline__ ull pack2(float lo, float hi) {
    ull d;
    asm("mov.b64 %0, {%1, %2};" : "=l"(d) : "f"(lo), "f"(hi));
    return d;
}
__device__ __forceinline__ void fma2(ull& d, ull a, ull b) {
    asm("fma.rn.f32x2 %0, %1, %2, %0;" : "+l"(d) : "l"(a), "l"(b));
}
__device__ __forceinline__ float2 unpack2(ull v) {
    float2 r;
    asm("mov.b64 {%0, %1}, %2;" : "=f"(r.x), "=f"(r.y) : "l"(v));
    return r;
}

// ---------------- Kernel A: build Q = H_0 H_1 ... H_127 per group ----------------
// Grid: 16 groups x 8 row-blocks = 128 blocks, 128 threads each.
// Thread (r, p): r = local row (16 rows/block), p = lane within 8-lane row team.
// Each thread owns 16 columns of its Q row (k = p + 8j), interleaved for
// conflict-free smem access. Per step: partial dot (16 FMA) -> 3x shfl_xor
// (width 8) -> rank-1 update (16 FMA). No __syncthreads in the scan.
__global__ void __launch_bounds__(128) buildq_kernel(const float* __restrict__ W) {
    extern __shared__ float sm[];
    float* WshT = sm;              // [128][129]  WshT[i][k] = W[g][k][i] (reflector i row)
    float* rden = sm + 128 * 129;  // [128]       2 / (w_i . w_i)

    const int g  = blockIdx.x >> 3;
    const int rb = blockIdx.x & 7;
    const float* Wg = W + (size_t)g * C * C;
    const int t = threadIdx.x;

    // Stage weight transposed: thread t owns reflector i = t.
    // Global reads coalesced (stride over k), smem writes at pitch 129 -> conflict-free.
    #pragma unroll 8
    for (int k = 0; k < C; k++) {
        WshT[t * 129 + k] = Wg[k * C + t];
    }
    __syncthreads();

    // rden[i] = 2 / sum_k w_i[k]^2
    {
        const float* row = &WshT[t * 129];
        float s = 0.0f;
        #pragma unroll 8
        for (int k = 0; k < C; k++) s = fmaf(row[k], row[k], s);
        rden[t] = 2.0f / s;
    }
    __syncthreads();

    const int r = t >> 3;
    const int p = t & 7;
    const int R = rb * 16 + r;  // global row of Q this team owns

    float M[16];
    #pragma unroll
    for (int j = 0; j < 16; j++) M[j] = (R == (p + 8 * j)) ? 1.0f : 0.0f;

    for (int i = 0; i < C; i++) {
        const float* wrow = &WshT[i * 129 + p];
        float wv[16];
        float d0 = 0.0f, d1 = 0.0f;
        #pragma unroll
        for (int j = 0; j < 16; j++) {
            wv[j] = wrow[8 * j];
            if (j & 1) d1 = fmaf(M[j], wv[j], d1);
            else       d0 = fmaf(M[j], wv[j], d0);
        }
        float d = d0 + d1;
        d += __shfl_xor_sync(0xffffffffu, d, 1, 8);
        d += __shfl_xor_sync(0xffffffffu, d, 2, 8);
        d += __shfl_xor_sync(0xffffffffu, d, 4, 8);
        const float c = d * rden[i];
        #pragma unroll
        for (int j = 0; j < 16; j++) M[j] = fmaf(-c, wv[j], M[j]);
    }

    float* Qrow = Qbuf + (size_t)g * C * C + R * C + p;
    #pragma unroll
    for (int j = 0; j < 16; j++) Qrow[8 * j] = M[j];
}

// ---------------- Kernel B: out[g] = x[g] @ Q[g] ----------------
// Block tile: 64 rows x 128 cols, full K=128 in smem.
// 256 threads: tx in [0,32) owns 4 n-cols, ty in [0,8) owns 8 m-rows.
// Accumulators are m-paired f32x2 (2 FMA per FFMA2 slot).
#define MTILE 64
#define SMEM_GEMM ((C * C + MTILE * C) * 4)  // 64KB Q + 32KB X = 96KB

__global__ void __launch_bounds__(256) gemm_kernel(const float* __restrict__ X,
                                                   float* __restrict__ Out) {
    extern __shared__ float smem[];
    float* Qs = smem;            // [128][128], n contiguous
    float* Xs = smem + C * C;    // [64][128],  k contiguous

    const int g  = blockIdx.y;
    const int m0 = blockIdx.x * MTILE;
    const int t  = threadIdx.x;

    const float4* Qg4 = (const float4*)(Qbuf + (size_t)g * C * C);
    float4* Qs4 = (float4*)Qs;
    #pragma unroll
    for (int it = 0; it < (C * C / 4) / 256; it++)
        Qs4[t + 256 * it] = Qg4[t + 256 * it];

    const float4* Xg4 = (const float4*)(X + ((size_t)g * MROWS + m0) * C);
    float4* Xs4 = (float4*)Xs;
    #pragma unroll
    for (int it = 0; it < (MTILE * C / 4) / 256; it++)
        Xs4[t + 256 * it] = Xg4[t + 256 * it];

    __syncthreads();

    const int tx = t & 31;        // n group
    const int ty = t >> 5;        // m group
    const int n0 = tx * 4;
    const int mb = ty * 8;

    ull acc[4][4];
    #pragma unroll
    for (int i = 0; i < 4; i++)
        #pragma unroll
        for (int j = 0; j < 4; j++) acc[i][j] = 0ull;

    const float* xbase = Xs + mb * C;

    for (int k4 = 0; k4 < C; k4 += 4) {
        float4 xq[8];
        #pragma unroll
        for (int mi = 0; mi < 8; mi++)
            xq[mi] = *(const float4*)(xbase + mi * C + k4);

        #pragma unroll
        for (int kk = 0; kk < 4; kk++) {
            const float4 q = *(const float4*)(Qs + (k4 + kk) * C + n0);
            ull qd[4];
            qd[0] = pack2(q.x, q.x);
            qd[1] = pack2(q.y, q.y);
            qd[2] = pack2(q.z, q.z);
            qd[3] = pack2(q.w, q.w);
            #pragma unroll
            for (int i = 0; i < 4; i++) {
                const float4 va = xq[2 * i];
                const float4 vb = xq[2 * i + 1];
                const float a = (kk == 0) ? va.x : (kk == 1) ? va.y : (kk == 2) ? va.z : va.w;
                const float b = (kk == 0) ? vb.x : (kk == 1) ? vb.y : (kk == 2) ? vb.z : vb.w;
                const ull xp = pack2(a, b);
                #pragma unroll
                for (int j = 0; j < 4; j++) fma2(acc[i][j], xp, qd[j]);
            }
        }
    }

    // Write out: each acc pair holds (m=2i, m=2i+1) for column n0+j.
    float* obase = Out + ((size_t)g * MROWS + m0 + mb) * C + n0;
    #pragma unroll
    for (int i = 0; i < 4; i++) {
        float lo[4], hi[4];
        #pragma unroll
        for (int j = 0; j < 4; j++) {
            const float2 v = unpack2(acc[i][j]);
            lo[j] = v.x;
            hi[j] = v.y;
        }
        *(float4*)(obase + (2 * i) * C)     = make_float4(lo[0], lo[1], lo[2], lo[3]);
        *(float4*)(obase + (2 * i + 1) * C) = make_float4(hi[0], hi[1], hi[2], hi[3]);
    }
}

// ---------------- launch ----------------
extern "C" void kernel_launch(void* const* d_in, const int* in_sizes, int n_in,
                              void* d_out, int out_size) {
    const float* x = (const float*)d_in[0];
    const float* w = (const float*)d_in[1];
    // Defensive: x is the big tensor (16*16384*128), weight is 16*128*128.
    if (n_in >= 2 && in_sizes[0] < in_sizes[1]) {
        const float* tmp = x; x = w; w = tmp;
    }
    float* out = (float*)d_out;

    const int smemA = 128 * 129 * 4 + 128 * 4;  // 66560
    cudaFuncSetAttribute((const void*)buildq_kernel,
                         cudaFuncAttributeMaxDynamicSharedMemorySize, smemA);
    cudaFuncSetAttribute((const void*)gemm_kernel,
                         cudaFuncAttributeMaxDynamicSharedMemorySize, SMEM_GEMM);

    buildq_kernel<<<G * 8, 128, smemA>>>(w);
    gemm_kernel<<<dim3(MROWS / MTILE, G), 256, SMEM_GEMM>>>(x, out);
}

// round 4
// speedup vs baseline: 1.9593x; 1.9593x over previous
#include <cuda_runtime.h>
#include <cuda_bf16.h>
#include <cstdint>

// out[g] = x[g] @ Q[g], Q = H_0..H_127 (Householder composition).
// Kernel A: build Q rows in parallel (rows evolve independently), emit Q
//           TRANSPOSED (k-major) as bf16 hi/lo pairs.
// Kernel B: warp-level mma.sync bf16 GEMM (sm_100-safe PTX), 3-product hi/lo
//           split for fp32-class accuracy.

#define G 16
#define MROWS 16384
#define C 128
#define MT 64          // m-tile per CTA
#define SP 136         // padded smem row stride in bf16 elements

__device__ __nv_bfloat16 Qt_hi[G * C * C];  // [g][n][k], k contiguous
__device__ __nv_bfloat16 Qt_lo[G * C * C];

__device__ __forceinline__ uint32_t smem_u32(const void* p) {
    uint32_t a;
    asm("{ .reg .u64 t; cvta.to.shared.u64 t, %1; cvt.u32.u64 %0, t; }"
        : "=r"(a) : "l"(p));
    return a;
}

__device__ __forceinline__ void ldmatrix_x4(uint32_t& r0, uint32_t& r1,
                                            uint32_t& r2, uint32_t& r3,
                                            uint32_t addr) {
    asm volatile("ldmatrix.sync.aligned.m8n8.x4.shared.b16 {%0,%1,%2,%3}, [%4];"
                 : "=r"(r0), "=r"(r1), "=r"(r2), "=r"(r3) : "r"(addr));
}

__device__ __forceinline__ void mma_bf16(float* d, const uint32_t* a,
                                         uint32_t b0, uint32_t b1) {
    asm volatile(
        "mma.sync.aligned.m16n8k16.row.col.f32.bf16.bf16.f32 "
        "{%0,%1,%2,%3}, {%4,%5,%6,%7}, {%8,%9}, {%0,%1,%2,%3};"
        : "+f"(d[0]), "+f"(d[1]), "+f"(d[2]), "+f"(d[3])
        : "r"(a[0]), "r"(a[1]), "r"(a[2]), "r"(a[3]), "r"(b0), "r"(b1));
}

// ==================== Kernel A: build Q (transposed, bf16 hi/lo) ====================
__global__ void __launch_bounds__(128) buildq_kernel(const float* __restrict__ W) {
    extern __shared__ float sm[];
    float* WshT = sm;              // [128][129]
    float* rden = sm + 128 * 129;  // [128]

    const int g  = blockIdx.x >> 3;
    const int rb = blockIdx.x & 7;
    const float* Wg = W + (size_t)g * C * C;
    const int t = threadIdx.x;

    #pragma unroll 8
    for (int k = 0; k < C; k++) WshT[t * 129 + k] = Wg[k * C + t];
    __syncthreads();

    {
        const float* row = &WshT[t * 129];
        float s = 0.0f;
        #pragma unroll 8
        for (int k = 0; k < C; k++) s = fmaf(row[k], row[k], s);
        rden[t] = 2.0f / s;
    }
    __syncthreads();

    const int r = t >> 3;
    const int p = t & 7;
    const int R = rb * 16 + r;  // row of Q (= K index of Q^T)

    float M[16];
    #pragma unroll
    for (int j = 0; j < 16; j++) M[j] = (R == (p + 8 * j)) ? 1.0f : 0.0f;

    for (int i = 0; i < C; i++) {
        const float* wrow = &WshT[i * 129 + p];
        float wv[16];
        float d0 = 0.0f, d1 = 0.0f;
        #pragma unroll
        for (int j = 0; j < 16; j++) {
            wv[j] = wrow[8 * j];
            if (j & 1) d1 = fmaf(M[j], wv[j], d1);
            else       d0 = fmaf(M[j], wv[j], d0);
        }
        float d = d0 + d1;
        d += __shfl_xor_sync(0xffffffffu, d, 1, 8);
        d += __shfl_xor_sync(0xffffffffu, d, 2, 8);
        d += __shfl_xor_sync(0xffffffffu, d, 4, 8);
        const float c = d * rden[i];
        #pragma unroll
        for (int j = 0; j < 16; j++) M[j] = fmaf(-c, wv[j], M[j]);
    }

    // Emit transposed: Qt[n][k] = Q[k][n]; n = p+8j (col of Q), k = R.
    #pragma unroll
    for (int j = 0; j < 16; j++) {
        const int n = p + 8 * j;
        const size_t idx = ((size_t)g * C + n) * C + R;
        __nv_bfloat16 hi = __float2bfloat16_rn(M[j]);
        __nv_bfloat16 lo = __float2bfloat16_rn(M[j] - __bfloat162float(hi));
        Qt_hi[idx] = hi;
        Qt_lo[idx] = lo;
    }
}

// ==================== Kernel B: mma.sync GEMM ====================
// Smem (bf16, padded stride SP):
//   Ah[MT][SP], Al[MT][SP]   : x tile hi/lo        (rows = m, k contiguous)
//   Bh[C][SP],  Bl[C][SP]    : Q^T hi/lo           (rows = n, k contiguous)
#define AH_OFF 0
#define AL_OFF (MT * SP * 2)
#define BH_OFF (2 * MT * SP * 2)
#define BL_OFF (2 * MT * SP * 2 + C * SP * 2)
#define SMEM_MMA (2 * MT * SP * 2 + 2 * C * SP * 2)   // 104448 bytes

__global__ void __launch_bounds__(128) mma_kernel(const float* __restrict__ X,
                                                  float* __restrict__ Out) {
    extern __shared__ char smem[];
    const uint32_t sb = smem_u32(smem);
    const int t  = threadIdx.x;
    const int w  = t >> 5;   // warp 0..3, owns m rows 16w..16w+15
    const int l  = t & 31;
    const int m0 = blockIdx.x * MT;
    const int g  = blockIdx.y;

    // ---- stage Q^T hi/lo (128 x 128 bf16 each), 8 bf16 per uint4 ----
    const uint4* qh = (const uint4*)(Qt_hi + (size_t)g * C * C);
    const uint4* ql = (const uint4*)(Qt_lo + (size_t)g * C * C);
    #pragma unroll
    for (int it = 0; it < 16; it++) {
        const int idx = t + 128 * it;
        const int row = idx >> 4;
        const int c8  = (idx & 15) * 8;
        const uint32_t off = (uint32_t)(row * SP + c8) * 2;
        *(uint4*)(smem + BH_OFF + off) = qh[idx];
        *(uint4*)(smem + BL_OFF + off) = ql[idx];
    }

    // ---- stage x tile -> bf16 hi/lo (64 x 128) ----
    const float4* xg = (const float4*)(X + ((size_t)g * MROWS + m0) * C);
    #pragma unroll
    for (int it = 0; it < 16; it++) {
        const int idx = t + 128 * it;          // float4 index
        const int row = idx >> 5;
        const int c4  = (idx & 31) * 4;
        const float4 v = xg[idx];
        const float vv[4] = {v.x, v.y, v.z, v.w};
        __nv_bfloat16 h[4], e[4];
        #pragma unroll
        for (int i = 0; i < 4; i++) {
            h[i] = __float2bfloat16_rn(vv[i]);
            e[i] = __float2bfloat16_rn(vv[i] - __bfloat162float(h[i]));
        }
        const uint32_t off = (uint32_t)(row * SP + c4) * 2;
        *(uint2*)(smem + AH_OFF + off) = *(const uint2*)h;
        *(uint2*)(smem + AL_OFF + off) = *(const uint2*)e;
    }

    __syncthreads();

    // ---- mainloop ----
    float acc[16][4];
    #pragma unroll
    for (int nt = 0; nt < 16; nt++)
        #pragma unroll
        for (int i = 0; i < 4; i++) acc[nt][i] = 0.0f;

    // ldmatrix lane address components
    const int a_row = 16 * w + (l & 7) + 8 * ((l >> 3) & 1);
    const int a_col8 = 8 * (l >> 4);
    const int b_row_in = (l & 7) + 8 * (l >> 4);
    const int b_col8 = 8 * ((l >> 3) & 1);

    #pragma unroll
    for (int ks = 0; ks < 8; ks++) {
        const int k0 = 16 * ks;
        uint32_t ah[4], al[4];
        {
            const uint32_t aoff = (uint32_t)(a_row * SP + k0 + a_col8) * 2;
            ldmatrix_x4(ah[0], ah[1], ah[2], ah[3], sb + AH_OFF + aoff);
            ldmatrix_x4(al[0], al[1], al[2], al[3], sb + AL_OFF + aoff);
        }
        #pragma unroll
        for (int j = 0; j < 8; j++) {
            const uint32_t boff =
                (uint32_t)((16 * j + b_row_in) * SP + k0 + b_col8) * 2;
            uint32_t bh0, bh1, bh2, bh3, bl0, bl1, bl2, bl3;
            ldmatrix_x4(bh0, bh1, bh2, bh3, sb + BH_OFF + boff);
            ldmatrix_x4(bl0, bl1, bl2, bl3, sb + BL_OFF + boff);
            // nt = 2j
            mma_bf16(acc[2 * j], ah, bh0, bh1);
            mma_bf16(acc[2 * j], ah, bl0, bl1);
            mma_bf16(acc[2 * j], al, bh0, bh1);
            // nt = 2j+1
            mma_bf16(acc[2 * j + 1], ah, bh2, bh3);
            mma_bf16(acc[2 * j + 1], ah, bl2, bl3);
            mma_bf16(acc[2 * j + 1], al, bh2, bh3);
        }
    }

    // ---- epilogue: fragment -> gmem ----
    // D fragment: d0,d1 at (row = l>>2, col = 2*(l&3)); d2,d3 at row+8.
    const int r0 = 16 * w + (l >> 2);
    const int cn = 2 * (l & 3);
    float* ob = Out + ((size_t)g * MROWS + m0 + r0) * C + cn;
    #pragma unroll
    for (int nt = 0; nt < 16; nt++) {
        *(float2*)(ob + 8 * nt)           = make_float2(acc[nt][0], acc[nt][1]);
        *(float2*)(ob + 8 * C + 8 * nt)   = make_float2(acc[nt][2], acc[nt][3]);
    }
}

// ==================== launch ====================
extern "C" void kernel_launch(void* const* d_in, const int* in_sizes, int n_in,
                              void* d_out, int out_size) {
    const float* x = (const float*)d_in[0];
    const float* w = (const float*)d_in[1];
    if (n_in >= 2 && in_sizes[0] < in_sizes[1]) {
        const float* tmp = x; x = w; w = tmp;
    }
    float* out = (float*)d_out;

    const int smemA = 128 * 129 * 4 + 128 * 4;  // 66560
    cudaFuncSetAttribute((const void*)buildq_kernel,
                         cudaFuncAttributeMaxDynamicSharedMemorySize, smemA);
    cudaFuncSetAttribute((const void*)mma_kernel,
                         cudaFuncAttributeMaxDynamicSharedMemorySize, SMEM_MMA);

    buildq_kernel<<<G * 8, 128, smemA>>>(w);
    mma_kernel<<<dim3(MROWS / MT, G), 128, SMEM_MMA>>>(x, out);
}